// round 12
// baseline (speedup 1.0000x reference)
#include <cuda_runtime.h>
#include <math.h>
#include <stdint.h>

#define BATCHN 4
#define SEQ    1024
#define DMODEL 1024
#define NHEAD  16
#define DHEAD  64
#define FFDIM  4096
#define NLAYER 4
#define MAXKLEN 1664
#define ROFF   640          // MAXKLEN - SEQ

// ---------------- scratch (device globals: allocation-free) ----------------
__device__ float g_X  [BATCHN*SEQ*DMODEL];   // residual stream (pure fp32)
__device__ float g_XR [BATCHN*SEQ*DMODEL];   // tf32-rounded copy of X
__device__ float g_QKV[BATCHN*SEQ*3*DMODEL]; // fused q|k|v (rounded), row stride 3072
__device__ float g_RQ [BATCHN*SEQ*DMODEL];   // q + r_w_bias (rounded)
__device__ float g_Q  [BATCHN*SEQ*DMODEL];   // Wo / FF2 outputs
__device__ float g_T  [BATCHN*SEQ*DMODEL];   // attention output
__device__ float g_P  [(size_t)BATCHN*NHEAD*SEQ*SEQ];  // q @ re^T + rb (skewed)
__device__ float g_H  [BATCHN*SEQ*FFDIM];              // FF hidden

// ---------------- helpers ----------------
__device__ __forceinline__ float gelu_exact(float x) {
    return 0.5f * x * (1.0f + erff(x * 0.70710678118654752f));
}

__device__ __forceinline__ float rnd_tf32(float x) {
    uint32_t u;
    asm("cvt.rna.tf32.f32 %0, %1;" : "=r"(u) : "f"(x));
    return __uint_as_float(u);
}

__device__ __forceinline__ void mma_tf32(float c[4],
                                         uint32_t a0, uint32_t a1, uint32_t a2, uint32_t a3,
                                         uint32_t b0, uint32_t b1) {
    asm volatile(
        "mma.sync.aligned.m16n8k8.row.col.f32.tf32.tf32.f32 "
        "{%0,%1,%2,%3}, {%4,%5,%6,%7}, {%8,%9}, {%0,%1,%2,%3};"
        : "+f"(c[0]), "+f"(c[1]), "+f"(c[2]), "+f"(c[3])
        : "r"(a0), "r"(a1), "r"(a2), "r"(a3), "r"(b0), "r"(b1));
}

__device__ __forceinline__ uint32_t sptr(const void* p) {
    return (uint32_t)__cvta_generic_to_shared(p);
}
__device__ __forceinline__ void cpasync16(uint32_t s, const void* g) {
    asm volatile("cp.async.cg.shared.global [%0], [%1], 16;\n" :: "r"(s), "l"(g));
}
__device__ __forceinline__ void cpcommit() { asm volatile("cp.async.commit_group;\n"); }

// ldmatrix of four 8x8 32-bit-granule tiles (b16 form, standard tf32 trick)
__device__ __forceinline__ void ldsm_x4(uint32_t& a, uint32_t& b,
                                        uint32_t& c, uint32_t& d, uint32_t addr) {
    asm volatile("ldmatrix.sync.aligned.m8n8.x4.shared.b16 {%0,%1,%2,%3}, [%4];"
                 : "=r"(a), "=r"(b), "=r"(c), "=r"(d) : "r"(addr));
}
// in-place tf32 rounding of a raw fragment
__device__ __forceinline__ void cvt_frag(uint32_t& u) {
    u = __float_as_uint(rnd_tf32(__uint_as_float(u)));
}

__device__ __forceinline__ float block_sum(float x, float* sm) {
    #pragma unroll
    for (int o = 16; o > 0; o >>= 1) x += __shfl_xor_sync(0xffffffffu, x, o);
    if ((threadIdx.x & 31) == 0) sm[threadIdx.x >> 5] = x;
    __syncthreads();
    float t = 0.f;
    #pragma unroll
    for (int w = 0; w < 8; w++) t += sm[w];
    __syncthreads();
    return t;
}

// ---------------- embed gather (pure + rounded copies) ----------------
__global__ void __launch_bounds__(256) k_embed(const int* __restrict__ seq,
                                               const float* __restrict__ emb,
                                               float* __restrict__ X,
                                               float* __restrict__ XR) {
    int row = blockIdx.x;
    int tok = seq[row];
    const float4* src = (const float4*)(emb + (size_t)tok * DMODEL);
    float4 v = src[threadIdx.x];
    ((float4*)(X + (size_t)row * DMODEL))[threadIdx.x] = v;
    v.x = rnd_tf32(v.x); v.y = rnd_tf32(v.y);
    v.z = rnd_tf32(v.z); v.w = rnd_tf32(v.w);
    ((float4*)(XR + (size_t)row * DMODEL))[threadIdx.x] = v;
}

// ---------------- TF32 tensor-core GEMM, 3-stage cp.async pipeline ---------
// C[M,N] = A[M,K] @ B[N,K]^T. Block 128x128x16, 256 thr = 2x4 warps.
// A-side operands arrive tf32-rounded (producer epilogues); B fragments are
// rounded in-loop (cvt_frag) so raw weights are consumed directly.
// Dynamic smem: As[3][128][20] | Bs[3][128][20] = 61440 B.
// Bk2/Bv2: fused-QKV weight segment select by n0>>10 (tiles never straddle).
// rqout: cols<1024 additionally write rnd(v + rwbv[c]). skew: skip bx+by<=6.
__global__ void __launch_bounds__(256) k_mma(
    int M, int N, int K,
    const float* __restrict__ A, int lda, long long sAb, long long sAh,
    const float* __restrict__ B, int ldb, long long sBb, long long sBh,
    float* __restrict__ C, int ldc, long long sCb, long long sCh,
    const float* __restrict__ bias, long long sbias_h,
    int Hdiv, int act, int rnd, int skew,
    float* __restrict__ rqout, const float* __restrict__ rwbv,
    const float* __restrict__ Bk2, const float* __restrict__ Bv2)
{
    if (skew && (int)(blockIdx.x + blockIdx.y) <= 6) return;

    constexpr int BM = 128, BN = 128, BK = 16;
    constexpr int AST = BK + 4;                 // 20
    constexpr int BST = BK + 4;
    extern __shared__ float smem[];
    float* As = smem;                           // [3][BM][AST]
    float* Bs = smem + 3 * BM * AST;            // [3][BN][BST]

    int z = blockIdx.z;
    int bb = z / Hdiv, hh = z % Hdiv;
    A += (long long)bb * sAb + (long long)hh * sAh;
    B += (long long)bb * sBb + (long long)hh * sBh;
    C += (long long)bb * sCb + (long long)hh * sCh;
    if (bias) bias += (long long)hh * sbias_h;

    const int tid  = threadIdx.x;
    const int lane = tid & 31, wid = tid >> 5;
    const int gid  = lane >> 2, tig = lane & 3;
    const int wm   = wid & 1,   wn  = wid >> 1;
    const int m0 = blockIdx.y * BM, n0 = blockIdx.x * BN;

    // fused-QKV weight segment select
    const float* Bp = B;
    int n0b = n0;
    if (Bk2) {
        int seg = n0 >> 10;
        if (seg == 1) Bp = Bk2; else if (seg == 2) Bp = Bv2;
        n0b = n0 & 1023;
    }

    float acc[4][4][4];
    #pragma unroll
    for (int i = 0; i < 4; i++)
        #pragma unroll
        for (int j = 0; j < 4; j++)
            #pragma unroll
            for (int q = 0; q < 4; q++) acc[i][j][q] = 0.f;

    const int iters = K / BK;

    auto stage = [&](int it, int buf) {
        int k0 = it * BK;
        float* Ab = As + buf * BM * AST;
        float* Bb = Bs + buf * BN * BST;
        #pragma unroll
        for (int i = 0; i < 2; i++) {           // 128*16/4/256 = 2
            int idx = tid + i * 256;
            int r = idx >> 2, c4 = idx & 3;
            cpasync16(sptr(&Ab[r * AST + c4 * 4]),
                      A + (long long)(m0 + r) * lda + k0 + c4 * 4);
        }
        #pragma unroll
        for (int i = 0; i < 2; i++) {
            int idx = tid + i * 256;
            int r = idx >> 2, c4 = idx & 3;
            cpasync16(sptr(&Bb[r * BST + c4 * 4]),
                      Bp + (long long)(n0b + r) * ldb + k0 + c4 * 4);
        }
        cpcommit();
    };

    const int a_row = lane & 15;
    const int a_koff = (lane >> 4) * 4;
    const int b_t = lane >> 3;
    const int b_j = lane & 7;

    auto compute = [&](int buf) {
        float* Ab = As + buf * BM * AST;
        float* Bb = Bs + buf * BN * BST;
        #pragma unroll
        for (int ks = 0; ks < 2; ks++) {
            int kk = ks * 8;
            uint32_t af[4][4], bf[4][2];
            #pragma unroll
            for (int mt = 0; mt < 4; mt++) {
                int rm = wm * 64 + mt * 16;
                ldsm_x4(af[mt][0], af[mt][1], af[mt][2], af[mt][3],
                        sptr(&Ab[(rm + a_row) * AST + kk + a_koff]));
            }
            #pragma unroll
            for (int np = 0; np < 2; np++) {
                int nb = wn * 32 + np * 16;
                ldsm_x4(bf[2 * np][0], bf[2 * np][1],
                        bf[2 * np + 1][0], bf[2 * np + 1][1],
                        sptr(&Bb[(nb + (b_t >> 1) * 8 + b_j) * BST
                                 + kk + (b_t & 1) * 4]));
            }
            #pragma unroll
            for (int nt = 0; nt < 4; nt++) {
                cvt_frag(bf[nt][0]); cvt_frag(bf[nt][1]);   // weights raw -> tf32
            }
            #pragma unroll
            for (int mt = 0; mt < 4; mt++)
                #pragma unroll
                for (int nt = 0; nt < 4; nt++)
                    mma_tf32(acc[mt][nt], af[mt][0], af[mt][1], af[mt][2], af[mt][3],
                             bf[nt][0], bf[nt][1]);
        }
    };

    stage(0, 0);
    stage(1, 1);
    for (int it = 0; it < iters; ++it) {
        if (it + 1 < iters) {
            asm volatile("cp.async.wait_group 1;\n");
        } else {
            asm volatile("cp.async.wait_group 0;\n");
        }
        __syncthreads();
        if (it + 2 < iters) stage(it + 2, (it + 2) % 3);
        compute(it % 3);
    }

    // epilogue
    #pragma unroll
    for (int mt = 0; mt < 4; mt++) {
        int r0 = m0 + wm * 64 + mt * 16 + gid;
        #pragma unroll
        for (int nt = 0; nt < 4; nt++) {
            int c = n0 + wn * 32 + nt * 8 + 2 * tig;
            float v0 = acc[mt][nt][0], v1 = acc[mt][nt][1];
            float v2 = acc[mt][nt][2], v3 = acc[mt][nt][3];
            if (bias) {
                float q0 = bias[c], q1 = bias[c + 1];
                v0 += q0; v1 += q1; v2 += q0; v3 += q1;
            }
            if (act) {
                v0 = gelu_exact(v0); v1 = gelu_exact(v1);
                v2 = gelu_exact(v2); v3 = gelu_exact(v3);
            }
            if (rnd) {
                v0 = rnd_tf32(v0); v1 = rnd_tf32(v1);
                v2 = rnd_tf32(v2); v3 = rnd_tf32(v3);
            }
            *(float2*)(C + (long long)r0 * ldc + c)       = make_float2(v0, v1);
            *(float2*)(C + (long long)(r0 + 8) * ldc + c) = make_float2(v2, v3);
            if (rqout && c < DMODEL) {
                float w0 = rwbv[c], w1 = rwbv[c + 1];
                *(float2*)(rqout + (long long)r0 * DMODEL + c) =
                    make_float2(rnd_tf32(v0 + w0), rnd_tf32(v1 + w1));
                *(float2*)(rqout + (long long)(r0 + 8) * DMODEL + c) =
                    make_float2(rnd_tf32(v2 + w0), rnd_tf32(v3 + w1));
            }
        }
    }
}

// ---------------- fused flash attention: softmax((RQ·K^T + shift(P))/4)·V ----
// 128 threads = 4 warps, each warp owns 16 query rows (BM=64 per CTA).
// Double-buffered K/V tiles via cp.async (dynamic smem 71680 B).
__global__ void __launch_bounds__(128) k_flash(
    const float* __restrict__ RQg, const float* __restrict__ Kg,
    const float* __restrict__ Vg,  const float* __restrict__ Pg,
    float* __restrict__ Tg, int ldkv)
{
    extern __shared__ float fsm[];
    float* KsB = fsm;                  // [2][64][68]; buf also holds p tile
    float* VsB = fsm + 2 * 64 * 68;    // [2][64][72]
    #define KS(b, r, c) KsB[(b) * 64 * 68 + (r) * 68 + (c)]
    #define VS(b, r, c) VsB[(b) * 64 * 72 + (r) * 72 + (c)]

    const int z  = blockIdx.y;             // b*H + h
    const int bb = z >> 4, hh = z & 15;
    const int m0 = blockIdx.x * 64;
    const float* rq = RQg + (size_t)bb * SEQ * DMODEL + hh * DHEAD;
    const float* kp = Kg  + (size_t)bb * SEQ * ldkv + hh * DHEAD;
    const float* vp = Vg  + (size_t)bb * SEQ * ldkv + hh * DHEAD;
    const float* pp = Pg  + (size_t)z * SEQ * SEQ;
    float*       tp = Tg  + (size_t)bb * SEQ * DMODEL + hh * DHEAD;

    const int tid = threadIdx.x, lane = tid & 31, wid = tid >> 5;
    const int gid = lane >> 2, tig = lane & 3;
    const int a_row = lane & 15, a_koff = (lane >> 4) * 4;
    const int b_t = lane >> 3, b_j = lane & 7;
    const int w16 = wid * 16;
    const int mg0 = m0 + w16 + gid, mg1 = mg0 + 8;

    // ---- stage RQ tile into Ks buf0, ldsm into registers ----
    #pragma unroll
    for (int i = 0; i < 8; i++) {
        int idx = tid + i * 128;
        int r = idx >> 4, c4 = idx & 15;
        cpasync16(sptr(&KS(0, r, c4 * 4)), rq + (size_t)(m0 + r) * DMODEL + c4 * 4);
    }
    cpcommit();
    asm volatile("cp.async.wait_group 0;\n");
    __syncthreads();
    uint32_t aq[8][4];
    #pragma unroll
    for (int ks = 0; ks < 8; ks++)
        ldsm_x4(aq[ks][0], aq[ks][1], aq[ks][2], aq[ks][3],
                sptr(&KS(0, w16 + a_row, ks * 8 + a_koff)));
    __syncthreads();   // aq reads done before buf0 is overwritten

    auto stage = [&](int nt, int b) {
        int n0 = nt * 64;
        #pragma unroll
        for (int i = 0; i < 8; i++) {
            int idx = tid + i * 128;
            int r = idx >> 4, c4 = idx & 15;
            cpasync16(sptr(&KS(b, r, c4 * 4)), kp + (size_t)(n0 + r) * ldkv + c4 * 4);
            cpasync16(sptr(&VS(b, r, c4 * 4)), vp + (size_t)(n0 + r) * ldkv + c4 * 4);
        }
        cpcommit();
    };

    float accO[8][4];
    #pragma unroll
    for (int ng = 0; ng < 8; ng++)
        #pragma unroll
        for (int q = 0; q < 4; q++) accO[ng][q] = 0.f;
    float mrow0 = -1e30f, mrow1 = -1e30f, lrow0 = 0.f, lrow1 = 0.f;

    stage(0, 0);
    for (int nt = 0; nt < SEQ / 64; nt++) {
        const int n0 = nt * 64;
        const int b = nt & 1;
        asm volatile("cp.async.wait_group 0;\n");   // tile nt loaded
        __syncthreads();                            // visible; prev compute done
        if (nt + 1 < SEQ / 64) stage(nt + 1, b ^ 1);  // overlaps compute(nt)

        // ---- S = RQ · K^T ----
        float S[8][4];
        #pragma unroll
        for (int ng = 0; ng < 8; ng++)
            #pragma unroll
            for (int q = 0; q < 4; q++) S[ng][q] = 0.f;
        #pragma unroll
        for (int ks = 0; ks < 8; ks++) {
            uint32_t bf[8][2];
            #pragma unroll
            for (int np = 0; np < 4; np++)
                ldsm_x4(bf[2 * np][0], bf[2 * np][1],
                        bf[2 * np + 1][0], bf[2 * np + 1][1],
                        sptr(&KS(b, np * 16 + (b_t >> 1) * 8 + b_j,
                                 ks * 8 + (b_t & 1) * 4)));
            #pragma unroll
            for (int ng = 0; ng < 8; ng++)
                mma_tf32(S[ng], aq[ks][0], aq[ks][1], aq[ks][2], aq[ks][3],
                         bf[ng][0], bf[ng][1]);
        }

        // ---- add shifted P, scale ----
        #pragma unroll
        for (int ng = 0; ng < 8; ng++) {
            int nc = n0 + ng * 8 + 2 * tig;
            float s0 = S[ng][0], s1 = S[ng][1], s2 = S[ng][2], s3 = S[ng][3];
            if (nc     <= mg0) s0 += pp[(size_t)mg0 * SEQ + (nc     - mg0 + SEQ - 1)];
            if (nc + 1 <= mg0) s1 += pp[(size_t)mg0 * SEQ + (nc + 1 - mg0 + SEQ - 1)];
            if (nc     <= mg1) s2 += pp[(size_t)mg1 * SEQ + (nc     - mg1 + SEQ - 1)];
            if (nc + 1 <= mg1) s3 += pp[(size_t)mg1 * SEQ + (nc + 1 - mg1 + SEQ - 1)];
            S[ng][0] = s0 * 0.25f; S[ng][1] = s1 * 0.25f;
            S[ng][2] = s2 * 0.25f; S[ng][3] = s3 * 0.25f;
        }

        // ---- online softmax update ----
        float tm0 = -1e30f, tm1 = -1e30f;
        #pragma unroll
        for (int ng = 0; ng < 8; ng++) {
            tm0 = fmaxf(tm0, fmaxf(S[ng][0], S[ng][1]));
            tm1 = fmaxf(tm1, fmaxf(S[ng][2], S[ng][3]));
        }
        tm0 = fmaxf(tm0, __shfl_xor_sync(0xffffffffu, tm0, 1));
        tm0 = fmaxf(tm0, __shfl_xor_sync(0xffffffffu, tm0, 2));
        tm1 = fmaxf(tm1, __shfl_xor_sync(0xffffffffu, tm1, 1));
        tm1 = fmaxf(tm1, __shfl_xor_sync(0xffffffffu, tm1, 2));
        float mn0 = fmaxf(mrow0, tm0), mn1 = fmaxf(mrow1, tm1);
        float al0 = __expf(mrow0 - mn0), al1 = __expf(mrow1 - mn1);
        mrow0 = mn0; mrow1 = mn1;
        float ts0 = 0.f, ts1 = 0.f;
        #pragma unroll
        for (int ng = 0; ng < 8; ng++) {
            S[ng][0] = __expf(S[ng][0] - mn0); ts0 += S[ng][0];
            S[ng][1] = __expf(S[ng][1] - mn0); ts0 += S[ng][1];
            S[ng][2] = __expf(S[ng][2] - mn1); ts1 += S[ng][2];
            S[ng][3] = __expf(S[ng][3] - mn1); ts1 += S[ng][3];
        }
        ts0 += __shfl_xor_sync(0xffffffffu, ts0, 1);
        ts0 += __shfl_xor_sync(0xffffffffu, ts0, 2);
        ts1 += __shfl_xor_sync(0xffffffffu, ts1, 1);
        ts1 += __shfl_xor_sync(0xffffffffu, ts1, 2);
        lrow0 = lrow0 * al0 + ts0;
        lrow1 = lrow1 * al1 + ts1;
        #pragma unroll
        for (int ng = 0; ng < 8; ng++) {
            accO[ng][0] *= al0; accO[ng][1] *= al0;
            accO[ng][2] *= al1; accO[ng][3] *= al1;
        }

        // ---- p tile -> smem (overlay Ks[b]), own-warp rows only ----
        __syncthreads();    // all warps done reading Ks[b]
        #pragma unroll
        for (int ng = 0; ng < 8; ng++) {
            *(float2*)&KS(b, w16 + gid,     ng * 8 + 2 * tig) =
                make_float2(rnd_tf32(S[ng][0]), rnd_tf32(S[ng][1]));
            *(float2*)&KS(b, w16 + gid + 8, ng * 8 + 2 * tig) =
                make_float2(rnd_tf32(S[ng][2]), rnd_tf32(S[ng][3]));
        }
        __syncwarp();

        // ---- O += p · V ----
        #pragma unroll
        for (int ks = 0; ks < 8; ks++) {
            uint32_t ap0, ap1, ap2, ap3;
            ldsm_x4(ap0, ap1, ap2, ap3,
                    sptr(&KS(b, w16 + a_row, ks * 8 + a_koff)));
            #pragma unroll
            for (int ng = 0; ng < 8; ng++) {
                uint32_t b0 = __float_as_uint(VS(b, ks * 8 + tig,     ng * 8 + gid));
                uint32_t b1 = __float_as_uint(VS(b, ks * 8 + tig + 4, ng * 8 + gid));
                mma_tf32(accO[ng], ap0, ap1, ap2, ap3, b0, b1);
            }
        }
    }

    // ---- normalize + write (rounded: feeds Wo GEMM) ----
    float i0 = 1.f / lrow0, i1 = 1.f / lrow1;
    #pragma unroll
    for (int ng = 0; ng < 8; ng++) {
        int c = ng * 8 + 2 * tig;
        *(float2*)(tp + (size_t)mg0 * DMODEL + c) =
            make_float2(rnd_tf32(accO[ng][0] * i0), rnd_tf32(accO[ng][1] * i0));
        *(float2*)(tp + (size_t)mg1 * DMODEL + c) =
            make_float2(rnd_tf32(accO[ng][2] * i1), rnd_tf32(accO[ng][3] * i1));
    }
    #undef KS
    #undef VS
}

// ---------------- residual add + LayerNorm (pure dst + rounded copy) -------
__global__ void __launch_bounds__(256) k_addln(const float* __restrict__ X,
                                               const float* __restrict__ R,
                                               const float* __restrict__ g,
                                               const float* __restrict__ b,
                                               float* __restrict__ dst,
                                               float* __restrict__ dstR) {
    int row = blockIdx.x;
    size_t base = (size_t)row * DMODEL;
    int tid = threadIdx.x;
    __shared__ float sm[8];

    float v[4];
    float s = 0.f;
    #pragma unroll
    for (int q = 0; q < 4; q++) {
        int c = q * 256 + tid;
        float x = X[base + c] + R[base + c];
        v[q] = x; s += x;
    }
    float mu = block_sum(s, sm) * (1.f / DMODEL);
    float s2 = 0.f;
    #pragma unroll
    for (int q = 0; q < 4; q++) { float d = v[q] - mu; s2 += d * d; }
    float var = block_sum(s2, sm) * (1.f / DMODEL);
    float rs = rsqrtf(var + 1e-5f);
    #pragma unroll
    for (int q = 0; q < 4; q++) {
        int c = q * 256 + tid;
        float y = (v[q] - mu) * rs * g[c] + b[c];
        dst[base + c] = y;
        dstR[base + c] = rnd_tf32(y);
    }
}

// ---------------- orchestration ----------------
extern "C" void kernel_launch(void* const* d_in, const int* in_sizes, int n_in,
                              void* d_out, int out_size) {
    (void)in_sizes; (void)n_in; (void)out_size;
    const int*   seq    = (const int*)  d_in[0];
    // d_in[1] mask (all true), d_in[2] cmems, d_in[3] mems: unused by reference
    const float* embed  = (const float*)d_in[4];
    const float* Wq     = (const float*)d_in[5];
    const float* Wk     = (const float*)d_in[6];
    const float* Wv     = (const float*)d_in[7];
    const float* Wo     = (const float*)d_in[8];
    const float* r_emb  = (const float*)d_in[9];
    const float* rwb    = (const float*)d_in[10];
    const float* r_bias = (const float*)d_in[11];
    const float* ln1g   = (const float*)d_in[12];
    const float* ln1b   = (const float*)d_in[13];
    const float* ln2g   = (const float*)d_in[14];
    const float* ln2b   = (const float*)d_in[15];
    const float* w1     = (const float*)d_in[16];
    const float* b1     = (const float*)d_in[17];
    const float* w2     = (const float*)d_in[18];
    const float* b2     = (const float*)d_in[19];

    float *X, *XR, *QKV, *RQ, *Q, *T, *P, *Hf;
    cudaGetSymbolAddress((void**)&X,   g_X);
    cudaGetSymbolAddress((void**)&XR,  g_XR);
    cudaGetSymbolAddress((void**)&QKV, g_QKV);
    cudaGetSymbolAddress((void**)&RQ,  g_RQ);
    cudaGetSymbolAddress((void**)&Q,   g_Q);
    cudaGetSymbolAddress((void**)&T,   g_T);
    cudaGetSymbolAddress((void**)&P,   g_P);
    cudaGetSymbolAddress((void**)&Hf,  g_H);

    static const int MMA_SMEM = 61440;
    static const int FLASH_SMEM = (2 * 64 * 68 + 2 * 64 * 72) * 4;   // 71680
    cudaFuncSetAttribute(k_mma, cudaFuncAttributeMaxDynamicSharedMemorySize, MMA_SMEM);
    cudaFuncSetAttribute(k_flash, cudaFuncAttributeMaxDynamicSharedMemorySize, FLASH_SMEM);

    const int M = BATCHN * SEQ;                       // 4096
    const size_t WSZ = (size_t)DMODEL * DMODEL;
    const long long sQKVb = (long long)SEQ * 3 * DMODEL;
    const long long sSCb  = (long long)NHEAD * SEQ * SEQ;
    const long long sSCh  = (long long)SEQ * SEQ;

    k_embed<<<M, 256>>>(seq, embed, X, XR);

    for (int l = 0; l < NLAYER; l++) {
        // fused QKV projection (N=3072, weight segments selected per CTA)
        dim3 gqkv(3 * DMODEL / 128, M / 128, 1);      // (24,32)
        k_mma<<<gqkv, 256, MMA_SMEM>>>(M, 3 * DMODEL, DMODEL,
                                       XR, DMODEL, 0, 0,
                                       Wq + l * WSZ, DMODEL, 0, 0,
                                       QKV, 3 * DMODEL, 0, 0,
                                       nullptr, 0, 1, 0, 1 /*rnd*/, 0,
                                       RQ, rwb + (size_t)l * NHEAD * DHEAD,
                                       Wk + l * WSZ, Wv + l * WSZ);

        // P = q @ re^T + rb (skewed); skip blocks never read (bx+by <= 6)
        dim3 gsc(SEQ / 128, SEQ / 128, BATCHN * NHEAD);
        k_mma<<<gsc, 256, MMA_SMEM>>>(SEQ, SEQ, DHEAD,
                                      QKV, 3 * DMODEL, sQKVb, DHEAD,
                                      r_emb + ((size_t)l * NHEAD * MAXKLEN + ROFF) * DHEAD,
                                      DHEAD, 0, (long long)MAXKLEN * DHEAD,
                                      P, SEQ, sSCb, sSCh,
                                      r_bias + (size_t)l * NHEAD * MAXKLEN + ROFF,
                                      MAXKLEN, NHEAD, 0, 0, 1,
                                      nullptr, nullptr, nullptr, nullptr);

        // fused attention: T = softmax((RQ K^T + shift(P))/4) V
        dim3 gfl(SEQ / 64, BATCHN * NHEAD, 1);
        k_flash<<<gfl, 128, FLASH_SMEM>>>(RQ, QKV + DMODEL, QKV + 2 * DMODEL, P, T,
                                          3 * DMODEL);

        // output projection -> Q, residual + LN1 -> X (+XR)
        dim3 gproj(DMODEL / 128, M / 128, 1);
        k_mma<<<gproj, 256, MMA_SMEM>>>(M, DMODEL, DMODEL, T, DMODEL, 0, 0,
                                        Wo + l * WSZ, DMODEL, 0, 0,
                                        Q, DMODEL, 0, 0,
                                        nullptr, 0, 1, 0, 0, 0,
                                        nullptr, nullptr, nullptr, nullptr);
        k_addln<<<M, 256>>>(X, Q, ln1g + (size_t)l * DMODEL, ln1b + (size_t)l * DMODEL,
                            X, XR);

        // FFN
        dim3 gff1(FFDIM / 128, M / 128, 1);
        k_mma<<<gff1, 256, MMA_SMEM>>>(M, FFDIM, DMODEL, XR, DMODEL, 0, 0,
                                       w1 + (size_t)l * FFDIM * DMODEL, DMODEL, 0, 0,
                                       Hf, FFDIM, 0, 0,
                                       b1 + (size_t)l * FFDIM, 0, 1, 1 /*gelu*/, 1, 0,
                                       nullptr, nullptr, nullptr, nullptr);
        dim3 gff2(DMODEL / 128, M / 128, 1);
        k_mma<<<gff2, 256, MMA_SMEM>>>(M, DMODEL, FFDIM, Hf, FFDIM, 0, 0,
                                       w2 + (size_t)l * DMODEL * FFDIM, FFDIM, 0, 0,
                                       Q, DMODEL, 0, 0,
                                       b2 + (size_t)l * DMODEL, 0, 1, 0, 0, 0,
                                       nullptr, nullptr, nullptr, nullptr);

        float* dst = (l == NLAYER - 1) ? (float*)d_out : X;
        k_addln<<<M, 256>>>(X, Q, ln2g + (size_t)l * DMODEL, ln2b + (size_t)l * DMODEL,
                            dst, XR);
    }
}

// round 13
// speedup vs baseline: 1.0986x; 1.0986x over previous
#include <cuda_runtime.h>
#include <math.h>
#include <stdint.h>

#define BATCHN 4
#define SEQ    1024
#define DMODEL 1024
#define NHEAD  16
#define DHEAD  64
#define FFDIM  4096
#define NLAYER 4
#define MAXKLEN 1664
#define ROFF   640          // MAXKLEN - SEQ

// ---------------- scratch (device globals: allocation-free) ----------------
__device__ float g_X  [BATCHN*SEQ*DMODEL];   // residual stream (pure fp32)
__device__ float g_XR [BATCHN*SEQ*DMODEL];   // tf32-rounded copy of X
__device__ float g_QKV[BATCHN*SEQ*3*DMODEL]; // fused q|k|v (rounded), row stride 3072
__device__ float g_RQ [BATCHN*SEQ*DMODEL];   // q + r_w_bias (rounded)
__device__ float g_Q  [BATCHN*SEQ*DMODEL];   // Wo / FF2 outputs
__device__ float g_T  [BATCHN*SEQ*DMODEL];   // attention output
__device__ float g_P  [(size_t)BATCHN*NHEAD*SEQ*SEQ + 64]; // q@re^T+rb (+pad)
__device__ float g_H  [BATCHN*SEQ*FFDIM];              // FF hidden
__device__ float g_WR [56u*1024*1024];                 // tf32-rounded weights

// offsets (floats) into g_WR
#define OFF_QKV 0u                      // [l][3*D][D] stacked wq|wk|wv
#define OFF_WO  (12u*1024*1024)
#define OFF_W1  (16u*1024*1024)
#define OFF_W2  (32u*1024*1024)
#define OFF_RE  (48u*1024*1024)
#define RE_SZ   (NLAYER*NHEAD*MAXKLEN*DHEAD)   // 6,815,744

// ---------------- helpers ----------------
__device__ __forceinline__ float gelu_exact(float x) {
    return 0.5f * x * (1.0f + erff(x * 0.70710678118654752f));
}

__device__ __forceinline__ float rnd_tf32(float x) {
    uint32_t u;
    asm("cvt.rna.tf32.f32 %0, %1;" : "=r"(u) : "f"(x));
    return __uint_as_float(u);
}

__device__ __forceinline__ void mma_tf32(float c[4],
                                         uint32_t a0, uint32_t a1, uint32_t a2, uint32_t a3,
                                         uint32_t b0, uint32_t b1) {
    asm volatile(
        "mma.sync.aligned.m16n8k8.row.col.f32.tf32.tf32.f32 "
        "{%0,%1,%2,%3}, {%4,%5,%6,%7}, {%8,%9}, {%0,%1,%2,%3};"
        : "+f"(c[0]), "+f"(c[1]), "+f"(c[2]), "+f"(c[3])
        : "r"(a0), "r"(a1), "r"(a2), "r"(a3), "r"(b0), "r"(b1));
}

__device__ __forceinline__ uint32_t sptr(const void* p) {
    return (uint32_t)__cvta_generic_to_shared(p);
}
__device__ __forceinline__ void cpasync16(uint32_t s, const void* g) {
    asm volatile("cp.async.cg.shared.global [%0], [%1], 16;\n" :: "r"(s), "l"(g));
}
__device__ __forceinline__ void cpcommit() { asm volatile("cp.async.commit_group;\n"); }

// ldmatrix of four 8x8 32-bit-granule tiles (b16 form, standard tf32 trick)
__device__ __forceinline__ void ldsm_x4(uint32_t& a, uint32_t& b,
                                        uint32_t& c, uint32_t& d, uint32_t addr) {
    asm volatile("ldmatrix.sync.aligned.m8n8.x4.shared.b16 {%0,%1,%2,%3}, [%4];"
                 : "=r"(a), "=r"(b), "=r"(c), "=r"(d) : "r"(addr));
}

__device__ __forceinline__ float block_sum(float x, float* sm) {
    #pragma unroll
    for (int o = 16; o > 0; o >>= 1) x += __shfl_xor_sync(0xffffffffu, x, o);
    if ((threadIdx.x & 31) == 0) sm[threadIdx.x >> 5] = x;
    __syncthreads();
    float t = 0.f;
    #pragma unroll
    for (int w = 0; w < 8; w++) t += sm[w];
    __syncthreads();
    return t;
}

// ---------------- tf32 pre-rounding ----------------
__global__ void __launch_bounds__(256) k_round(const float4* __restrict__ src,
                                               float4* __restrict__ dst, int n4) {
    int i = blockIdx.x * blockDim.x + threadIdx.x;
    if (i < n4) {
        float4 v = src[i];
        v.x = rnd_tf32(v.x); v.y = rnd_tf32(v.y);
        v.z = rnd_tf32(v.z); v.w = rnd_tf32(v.w);
        dst[i] = v;
    }
}

// ---------------- embed gather (pure + rounded copies) ----------------
__global__ void __launch_bounds__(256) k_embed(const int* __restrict__ seq,
                                               const float* __restrict__ emb,
                                               float* __restrict__ X,
                                               float* __restrict__ XR) {
    int row = blockIdx.x;
    int tok = seq[row];
    const float4* src = (const float4*)(emb + (size_t)tok * DMODEL);
    float4 v = src[threadIdx.x];
    ((float4*)(X + (size_t)row * DMODEL))[threadIdx.x] = v;
    v.x = rnd_tf32(v.x); v.y = rnd_tf32(v.y);
    v.z = rnd_tf32(v.z); v.w = rnd_tf32(v.w);
    ((float4*)(XR + (size_t)row * DMODEL))[threadIdx.x] = v;
}

// ---------------- TF32 tensor-core GEMM, 3-stage cp.async pipeline ---------
// C[M,N] = A[M,K] @ B[N,K]^T. Block 128x128x16, 256 thr = 2x4 warps.
// All operands pre-rounded tf32 bit patterns -> mainloop is ldsm+MMA only.
// Dynamic smem: As[3][128][20] | Bs[3][128][20] = 61440 B.
// rqout: cols<1024 additionally write rnd(v + rwbv[c]). skew: skip bx+by<=6.
__global__ void __launch_bounds__(256) k_mma(
    int M, int N, int K,
    const float* __restrict__ A, int lda, long long sAb, long long sAh,
    const float* __restrict__ B, int ldb, long long sBb, long long sBh,
    float* __restrict__ C, int ldc, long long sCb, long long sCh,
    const float* __restrict__ bias, long long sbias_h,
    int Hdiv, int act, int rnd, int skew,
    float* __restrict__ rqout, const float* __restrict__ rwbv)
{
    if (skew && (int)(blockIdx.x + blockIdx.y) <= 6) return;

    constexpr int BM = 128, BN = 128, BK = 16;
    constexpr int AST = BK + 4;                 // 20
    constexpr int BST = BK + 4;
    extern __shared__ float smem[];
    float* As = smem;                           // [3][BM][AST]
    float* Bs = smem + 3 * BM * AST;            // [3][BN][BST]

    int z = blockIdx.z;
    int bb = z / Hdiv, hh = z % Hdiv;
    A += (long long)bb * sAb + (long long)hh * sAh;
    B += (long long)bb * sBb + (long long)hh * sBh;
    C += (long long)bb * sCb + (long long)hh * sCh;
    if (bias) bias += (long long)hh * sbias_h;

    const int tid  = threadIdx.x;
    const int lane = tid & 31, wid = tid >> 5;
    const int gid  = lane >> 2, tig = lane & 3;
    const int wm   = wid & 1,   wn  = wid >> 1;
    const int m0 = blockIdx.y * BM, n0 = blockIdx.x * BN;

    float acc[4][4][4];
    #pragma unroll
    for (int i = 0; i < 4; i++)
        #pragma unroll
        for (int j = 0; j < 4; j++)
            #pragma unroll
            for (int q = 0; q < 4; q++) acc[i][j][q] = 0.f;

    const int iters = K / BK;

    auto stage = [&](int it, int buf) {
        int k0 = it * BK;
        float* Ab = As + buf * BM * AST;
        float* Bb = Bs + buf * BN * BST;
        #pragma unroll
        for (int i = 0; i < 2; i++) {           // 128*16/4/256 = 2
            int idx = tid + i * 256;
            int r = idx >> 2, c4 = idx & 3;
            cpasync16(sptr(&Ab[r * AST + c4 * 4]),
                      A + (long long)(m0 + r) * lda + k0 + c4 * 4);
        }
        #pragma unroll
        for (int i = 0; i < 2; i++) {
            int idx = tid + i * 256;
            int r = idx >> 2, c4 = idx & 3;
            cpasync16(sptr(&Bb[r * BST + c4 * 4]),
                      B + (long long)(n0 + r) * ldb + k0 + c4 * 4);
        }
        cpcommit();
    };

    const int a_row = lane & 15;
    const int a_koff = (lane >> 4) * 4;
    const int b_t = lane >> 3;
    const int b_j = lane & 7;

    auto compute = [&](int buf) {
        float* Ab = As + buf * BM * AST;
        float* Bb = Bs + buf * BN * BST;
        #pragma unroll
        for (int ks = 0; ks < 2; ks++) {
            int kk = ks * 8;
            uint32_t af[4][4], bf[4][2];
            #pragma unroll
            for (int mt = 0; mt < 4; mt++) {
                int rm = wm * 64 + mt * 16;
                ldsm_x4(af[mt][0], af[mt][1], af[mt][2], af[mt][3],
                        sptr(&Ab[(rm + a_row) * AST + kk + a_koff]));
            }
            #pragma unroll
            for (int np = 0; np < 2; np++) {
                int nb = wn * 32 + np * 16;
                ldsm_x4(bf[2 * np][0], bf[2 * np][1],
                        bf[2 * np + 1][0], bf[2 * np + 1][1],
                        sptr(&Bb[(nb + (b_t >> 1) * 8 + b_j) * BST
                                 + kk + (b_t & 1) * 4]));
            }
            #pragma unroll
            for (int mt = 0; mt < 4; mt++)
                #pragma unroll
                for (int nt = 0; nt < 4; nt++)
                    mma_tf32(acc[mt][nt], af[mt][0], af[mt][1], af[mt][2], af[mt][3],
                             bf[nt][0], bf[nt][1]);
        }
    };

    stage(0, 0);
    stage(1, 1);
    for (int it = 0; it < iters; ++it) {
        if (it + 1 < iters) {
            asm volatile("cp.async.wait_group 1;\n");
        } else {
            asm volatile("cp.async.wait_group 0;\n");
        }
        __syncthreads();
        if (it + 2 < iters) stage(it + 2, (it + 2) % 3);
        compute(it % 3);
    }

    // epilogue
    #pragma unroll
    for (int mt = 0; mt < 4; mt++) {
        int r0 = m0 + wm * 64 + mt * 16 + gid;
        #pragma unroll
        for (int nt = 0; nt < 4; nt++) {
            int c = n0 + wn * 32 + nt * 8 + 2 * tig;
            float v0 = acc[mt][nt][0], v1 = acc[mt][nt][1];
            float v2 = acc[mt][nt][2], v3 = acc[mt][nt][3];
            if (bias) {
                float q0 = bias[c], q1 = bias[c + 1];
                v0 += q0; v1 += q1; v2 += q0; v3 += q1;
            }
            if (act) {
                v0 = gelu_exact(v0); v1 = gelu_exact(v1);
                v2 = gelu_exact(v2); v3 = gelu_exact(v3);
            }
            if (rnd) {
                v0 = rnd_tf32(v0); v1 = rnd_tf32(v1);
                v2 = rnd_tf32(v2); v3 = rnd_tf32(v3);
            }
            *(float2*)(C + (long long)r0 * ldc + c)       = make_float2(v0, v1);
            *(float2*)(C + (long long)(r0 + 8) * ldc + c) = make_float2(v2, v3);
            if (rqout && c < DMODEL) {
                float w0 = rwbv[c], w1 = rwbv[c + 1];
                *(float2*)(rqout + (long long)r0 * DMODEL + c) =
                    make_float2(rnd_tf32(v0 + w0), rnd_tf32(v1 + w1));
                *(float2*)(rqout + (long long)(r0 + 8) * DMODEL + c) =
                    make_float2(rnd_tf32(v2 + w0), rnd_tf32(v3 + w1));
            }
        }
    }
}

// ---------------- fused flash attention: softmax((RQ·K^T + shift(P))/4)·V ----
// 128 threads = 4 warps, each warp owns 16 query rows (BM=64 per CTA).
// Double-buffered K/V/P staging via cp.async; P band prefetched to smem.
// Dynamic smem: Ks[2][64][68] | Vs[2][64][72] | Ps[2][64][72] = 108544 B.
__global__ void __launch_bounds__(128) k_flash(
    const float* __restrict__ RQg, const float* __restrict__ Kg,
    const float* __restrict__ Vg,  const float* __restrict__ Pg,
    float* __restrict__ Tg, int ldkv)
{
    extern __shared__ float fsm[];
    float* KsB = fsm;                         // [2][64][68]; buf also holds p tile
    float* VsB = fsm + 2 * 64 * 68;           // [2][64][72]
    float* PsB = fsm + 2 * 64 * 68 + 2 * 64 * 72;  // [2][64][72] staged P band
    #define KS(b, r, c) KsB[(b) * 64 * 68 + (r) * 68 + (c)]
    #define VS(b, r, c) VsB[(b) * 64 * 72 + (r) * 72 + (c)]
    #define PS(b, r, c) PsB[(b) * 64 * 72 + (r) * 72 + (c)]

    const int z  = blockIdx.y;             // b*H + h
    const int bb = z >> 4, hh = z & 15;
    const int m0 = blockIdx.x * 64;
    const float* rq = RQg + (size_t)bb * SEQ * DMODEL + hh * DHEAD;
    const float* kp = Kg  + (size_t)bb * SEQ * ldkv + hh * DHEAD;
    const float* vp = Vg  + (size_t)bb * SEQ * ldkv + hh * DHEAD;
    const float* pp = Pg  + (size_t)z * SEQ * SEQ;
    float*       tp = Tg  + (size_t)bb * SEQ * DMODEL + hh * DHEAD;

    const int tid = threadIdx.x, lane = tid & 31, wid = tid >> 5;
    const int gid = lane >> 2, tig = lane & 3;
    const int a_row = lane & 15, a_koff = (lane >> 4) * 4;
    const int b_t = lane >> 3, b_j = lane & 7;
    const int w16 = wid * 16;
    const int mg0 = m0 + w16 + gid, mg1 = mg0 + 8;
    const int offp = (1023 - mg0) & 3;     // P band alignment offset (== for mg1)

    // ---- stage RQ tile into Ks buf0, ldsm into registers ----
    #pragma unroll
    for (int i = 0; i < 8; i++) {
        int idx = tid + i * 128;
        int r = idx >> 4, c4 = idx & 15;
        cpasync16(sptr(&KS(0, r, c4 * 4)), rq + (size_t)(m0 + r) * DMODEL + c4 * 4);
    }
    cpcommit();
    asm volatile("cp.async.wait_group 0;\n");
    __syncthreads();
    uint32_t aq[8][4];
    #pragma unroll
    for (int ks = 0; ks < 8; ks++)
        ldsm_x4(aq[ks][0], aq[ks][1], aq[ks][2], aq[ks][3],
                sptr(&KS(0, w16 + a_row, ks * 8 + a_koff)));
    __syncthreads();   // aq reads done before buf0 is overwritten

    // stage K/V tile + P band for key-tile nt into buffer b
    auto stage = [&](int nt, int b) {
        int n0 = nt * 64;
        #pragma unroll
        for (int i = 0; i < 8; i++) {
            int idx = tid + i * 128;
            int r = idx >> 4, c4 = idx & 15;
            cpasync16(sptr(&KS(b, r, c4 * 4)), kp + (size_t)(n0 + r) * ldkv + c4 * 4);
            cpasync16(sptr(&VS(b, r, c4 * 4)), vp + (size_t)(n0 + r) * ldkv + c4 * 4);
        }
        // P band: row r needs cols [n0-(m0+r)+1023 ...]; stage 68 floats from
        // the 16B-aligned floor. 64 rows x 17 chunks = 1088 chunks.
        #pragma unroll
        for (int i = 0; i < 9; i++) {
            int idx = tid + i * 128;
            if (idx < 1088) {
                int r = idx / 17, ch = idx % 17;
                int m = m0 + r;
                int cs = n0 - m + 1023;
                int as = cs & ~3;
                cpasync16(sptr(&PS(b, r, ch * 4)),
                          pp + (size_t)m * SEQ + as + ch * 4);
            }
        }
        cpcommit();
    };

    float accO[8][4];
    #pragma unroll
    for (int ng = 0; ng < 8; ng++)
        #pragma unroll
        for (int q = 0; q < 4; q++) accO[ng][q] = 0.f;
    float mrow0 = -1e30f, mrow1 = -1e30f, lrow0 = 0.f, lrow1 = 0.f;

    stage(0, 0);
    for (int nt = 0; nt < SEQ / 64; nt++) {
        const int n0 = nt * 64;
        const int b = nt & 1;
        asm volatile("cp.async.wait_group 0;\n");   // tile nt loaded
        __syncthreads();                            // visible; prev compute done
        if (nt + 1 < SEQ / 64) stage(nt + 1, b ^ 1);  // overlaps compute(nt)

        // ---- S = RQ · K^T ----
        float S[8][4];
        #pragma unroll
        for (int ng = 0; ng < 8; ng++)
            #pragma unroll
            for (int q = 0; q < 4; q++) S[ng][q] = 0.f;
        #pragma unroll
        for (int ks = 0; ks < 8; ks++) {
            uint32_t bf[8][2];
            #pragma unroll
            for (int np = 0; np < 4; np++)
                ldsm_x4(bf[2 * np][0], bf[2 * np][1],
                        bf[2 * np + 1][0], bf[2 * np + 1][1],
                        sptr(&KS(b, np * 16 + (b_t >> 1) * 8 + b_j,
                                 ks * 8 + (b_t & 1) * 4)));
            #pragma unroll
            for (int ng = 0; ng < 8; ng++)
                mma_tf32(S[ng], aq[ks][0], aq[ks][1], aq[ks][2], aq[ks][3],
                         bf[ng][0], bf[ng][1]);
        }

        // ---- add shifted P (from staged smem band), scale ----
        #pragma unroll
        for (int ng = 0; ng < 8; ng++) {
            int j = ng * 8 + 2 * tig;
            int nc = n0 + j;
            float p0 = PS(b, w16 + gid,     offp + j);
            float p1 = PS(b, w16 + gid,     offp + j + 1);
            float p2 = PS(b, w16 + gid + 8, offp + j);
            float p3 = PS(b, w16 + gid + 8, offp + j + 1);
            float s0 = S[ng][0], s1 = S[ng][1], s2 = S[ng][2], s3 = S[ng][3];
            if (nc     <= mg0) s0 += p0;
            if (nc + 1 <= mg0) s1 += p1;
            if (nc     <= mg1) s2 += p2;
            if (nc + 1 <= mg1) s3 += p3;
            S[ng][0] = s0 * 0.25f; S[ng][1] = s1 * 0.25f;
            S[ng][2] = s2 * 0.25f; S[ng][3] = s3 * 0.25f;
        }

        // ---- online softmax update ----
        float tm0 = -1e30f, tm1 = -1e30f;
        #pragma unroll
        for (int ng = 0; ng < 8; ng++) {
            tm0 = fmaxf(tm0, fmaxf(S[ng][0], S[ng][1]));
            tm1 = fmaxf(tm1, fmaxf(S[ng][2], S[ng][3]));
        }
        tm0 = fmaxf(tm0, __shfl_xor_sync(0xffffffffu, tm0, 1));
        tm0 = fmaxf(tm0, __shfl_xor_sync(0xffffffffu, tm0, 2));
        tm1 = fmaxf(tm1, __shfl_xor_sync(0xffffffffu, tm1, 1));
        tm1 = fmaxf(tm1, __shfl_xor_sync(0xffffffffu, tm1, 2));
        float mn0 = fmaxf(mrow0, tm0), mn1 = fmaxf(mrow1, tm1);
        float al0 = __expf(mrow0 - mn0), al1 = __expf(mrow1 - mn1);
        mrow0 = mn0; mrow1 = mn1;
        float ts0 = 0.f, ts1 = 0.f;
        #pragma unroll
        for (int ng = 0; ng < 8; ng++) {
            S[ng][0] = __expf(S[ng][0] - mn0); ts0 += S[ng][0];
            S[ng][1] = __expf(S[ng][1] - mn0); ts0 += S[ng][1];
            S[ng][2] = __expf(S[ng][2] - mn1); ts1 += S[ng][2];
            S[ng][3] = __expf(S[ng][3] - mn1); ts1 += S[ng][3];
        }
        ts0 += __shfl_xor_sync(0xffffffffu, ts0, 1);
        ts0 += __shfl_xor_sync(0xffffffffu, ts0, 2);
        ts1 += __shfl_xor_sync(0xffffffffu, ts1, 1);
        ts1 += __shfl_xor_sync(0xffffffffu, ts1, 2);
        lrow0 = lrow0 * al0 + ts0;
        lrow1 = lrow1 * al1 + ts1;
        #pragma unroll
        for (int ng = 0; ng < 8; ng++) {
            accO[ng][0] *= al0; accO[ng][1] *= al0;
            accO[ng][2] *= al1; accO[ng][3] *= al1;
        }

        // ---- p tile -> smem (overlay Ks[b]), own-warp rows only ----
        __syncthreads();    // all warps done reading Ks[b]
        #pragma unroll
        for (int ng = 0; ng < 8; ng++) {
            *(float2*)&KS(b, w16 + gid,     ng * 8 + 2 * tig) =
                make_float2(rnd_tf32(S[ng][0]), rnd_tf32(S[ng][1]));
            *(float2*)&KS(b, w16 + gid + 8, ng * 8 + 2 * tig) =
                make_float2(rnd_tf32(S[ng][2]), rnd_tf32(S[ng][3]));
        }
        __syncwarp();

        // ---- O += p · V ----
        #pragma unroll
        for (int ks = 0; ks < 8; ks++) {
            uint32_t ap0, ap1, ap2, ap3;
            ldsm_x4(ap0, ap1, ap2, ap3,
                    sptr(&KS(b, w16 + a_row, ks * 8 + a_koff)));
            #pragma unroll
            for (int ng = 0; ng < 8; ng++) {
                uint32_t b0 = __float_as_uint(VS(b, ks * 8 + tig,     ng * 8 + gid));
                uint32_t b1 = __float_as_uint(VS(b, ks * 8 + tig + 4, ng * 8 + gid));
                mma_tf32(accO[ng], ap0, ap1, ap2, ap3, b0, b1);
            }
        }
    }

    // ---- normalize + write (rounded: feeds Wo GEMM) ----
    float i0 = 1.f / lrow0, i1 = 1.f / lrow1;
    #pragma unroll
    for (int ng = 0; ng < 8; ng++) {
        int c = ng * 8 + 2 * tig;
        *(float2*)(tp + (size_t)mg0 * DMODEL + c) =
            make_float2(rnd_tf32(accO[ng][0] * i0), rnd_tf32(accO[ng][1] * i0));
        *(float2*)(tp + (size_t)mg1 * DMODEL + c) =
            make_float2(rnd_tf32(accO[ng][2] * i1), rnd_tf32(accO[ng][3] * i1));
    }
    #undef KS
    #undef VS
    #undef PS
}

// ---------------- residual add + LayerNorm (pure dst + rounded copy) -------
__global__ void __launch_bounds__(256) k_addln(const float* __restrict__ X,
                                               const float* __restrict__ R,
                                               const float* __restrict__ g,
                                               const float* __restrict__ b,
                                               float* __restrict__ dst,
                                               float* __restrict__ dstR) {
    int row = blockIdx.x;
    size_t base = (size_t)row * DMODEL;
    int tid = threadIdx.x;
    __shared__ float sm[8];

    float v[4];
    float s = 0.f;
    #pragma unroll
    for (int q = 0; q < 4; q++) {
        int c = q * 256 + tid;
        float x = X[base + c] + R[base + c];
        v[q] = x; s += x;
    }
    float mu = block_sum(s, sm) * (1.f / DMODEL);
    float s2 = 0.f;
    #pragma unroll
    for (int q = 0; q < 4; q++) { float d = v[q] - mu; s2 += d * d; }
    float var = block_sum(s2, sm) * (1.f / DMODEL);
    float rs = rsqrtf(var + 1e-5f);
    #pragma unroll
    for (int q = 0; q < 4; q++) {
        int c = q * 256 + tid;
        float y = (v[q] - mu) * rs * g[c] + b[c];
        dst[base + c] = y;
        dstR[base + c] = rnd_tf32(y);
    }
}

// ---------------- orchestration ----------------
extern "C" void kernel_launch(void* const* d_in, const int* in_sizes, int n_in,
                              void* d_out, int out_size) {
    (void)in_sizes; (void)n_in; (void)out_size;
    const int*   seq    = (const int*)  d_in[0];
    // d_in[1] mask (all true), d_in[2] cmems, d_in[3] mems: unused by reference
    const float* embed  = (const float*)d_in[4];
    const float* Wq     = (const float*)d_in[5];
    const float* Wk     = (const float*)d_in[6];
    const float* Wv     = (const float*)d_in[7];
    const float* Wo     = (const float*)d_in[8];
    const float* r_emb  = (const float*)d_in[9];
    const float* rwb    = (const float*)d_in[10];
    const float* r_bias = (const float*)d_in[11];
    const float* ln1g   = (const float*)d_in[12];
    const float* ln1b   = (const float*)d_in[13];
    const float* ln2g   = (const float*)d_in[14];
    const float* ln2b   = (const float*)d_in[15];
    const float* w1     = (const float*)d_in[16];
    const float* b1     = (const float*)d_in[17];
    const float* w2     = (const float*)d_in[18];
    const float* b2     = (const float*)d_in[19];

    float *X, *XR, *QKV, *RQ, *Q, *T, *P, *Hf, *WR;
    cudaGetSymbolAddress((void**)&X,   g_X);
    cudaGetSymbolAddress((void**)&XR,  g_XR);
    cudaGetSymbolAddress((void**)&QKV, g_QKV);
    cudaGetSymbolAddress((void**)&RQ,  g_RQ);
    cudaGetSymbolAddress((void**)&Q,   g_Q);
    cudaGetSymbolAddress((void**)&T,   g_T);
    cudaGetSymbolAddress((void**)&P,   g_P);
    cudaGetSymbolAddress((void**)&Hf,  g_H);
    cudaGetSymbolAddress((void**)&WR,  g_WR);

    static const int MMA_SMEM = 61440;
    static const int FLASH_SMEM = (2 * 64 * 68 + 2 * 64 * 72 + 2 * 64 * 72) * 4; // 108544
    cudaFuncSetAttribute(k_mma, cudaFuncAttributeMaxDynamicSharedMemorySize, MMA_SMEM);
    cudaFuncSetAttribute(k_flash, cudaFuncAttributeMaxDynamicSharedMemorySize, FLASH_SMEM);

    auto roundArr = [&](const float* src, float* dst, size_t n) {
        int n4 = (int)(n / 4);
        k_round<<<(n4 + 255) / 256, 256>>>((const float4*)src, (float4*)dst, n4);
    };
    // stack wq|wk|wv per layer into [3*D, D]
    const size_t WSZ = (size_t)DMODEL * DMODEL;
    for (int l = 0; l < NLAYER; l++) {
        float* dst = WR + OFF_QKV + (size_t)l * 3 * WSZ;
        roundArr(Wq + (size_t)l * WSZ, dst,           WSZ);
        roundArr(Wk + (size_t)l * WSZ, dst + WSZ,     WSZ);
        roundArr(Wv + (size_t)l * WSZ, dst + 2 * WSZ, WSZ);
    }
    roundArr(Wo, WR + OFF_WO, (size_t)NLAYER * WSZ);
    roundArr(w1, WR + OFF_W1, (size_t)NLAYER * FFDIM * DMODEL);
    roundArr(w2, WR + OFF_W2, (size_t)NLAYER * DMODEL * FFDIM);
    roundArr(r_emb, WR + OFF_RE, (size_t)RE_SZ);

    const int M = BATCHN * SEQ;                       // 4096
    const long long sQKVb = (long long)SEQ * 3 * DMODEL;
    const long long sSCb  = (long long)NHEAD * SEQ * SEQ;
    const long long sSCh  = (long long)SEQ * SEQ;

    k_embed<<<M, 256>>>(seq, embed, X, XR);

    for (int l = 0; l < NLAYER; l++) {
        // fused QKV projection (N=3072) + rwb epilogue -> RQ
        dim3 gqkv(3 * DMODEL / 128, M / 128, 1);      // (24,32)
        k_mma<<<gqkv, 256, MMA_SMEM>>>(M, 3 * DMODEL, DMODEL,
                                       XR, DMODEL, 0, 0,
                                       WR + OFF_QKV + (size_t)l * 3 * WSZ, DMODEL, 0, 0,
                                       QKV, 3 * DMODEL, 0, 0,
                                       nullptr, 0, 1, 0, 1 /*rnd*/, 0,
                                       RQ, rwb + (size_t)l * NHEAD * DHEAD);

        // P = q @ re^T + rb (skewed); skip blocks never read (bx+by <= 6)
        dim3 gsc(SEQ / 128, SEQ / 128, BATCHN * NHEAD);
        k_mma<<<gsc, 256, MMA_SMEM>>>(SEQ, SEQ, DHEAD,
                                      QKV, 3 * DMODEL, sQKVb, DHEAD,
                                      WR + OFF_RE + ((size_t)l * NHEAD * MAXKLEN + ROFF) * DHEAD,
                                      DHEAD, 0, (long long)MAXKLEN * DHEAD,
                                      P, SEQ, sSCb, sSCh,
                                      r_bias + (size_t)l * NHEAD * MAXKLEN + ROFF,
                                      MAXKLEN, NHEAD, 0, 0, 1, nullptr, nullptr);

        // fused attention: T = softmax((RQ K^T + shift(P))/4) V
        dim3 gfl(SEQ / 64, BATCHN * NHEAD, 1);
        k_flash<<<gfl, 128, FLASH_SMEM>>>(RQ, QKV + DMODEL, QKV + 2 * DMODEL, P, T,
                                          3 * DMODEL);

        // output projection -> Q, residual + LN1 -> X (+XR)
        dim3 gproj(DMODEL / 128, M / 128, 1);
        k_mma<<<gproj, 256, MMA_SMEM>>>(M, DMODEL, DMODEL, T, DMODEL, 0, 0,
                                        WR + OFF_WO + (size_t)l * WSZ, DMODEL, 0, 0,
                                        Q, DMODEL, 0, 0,
                                        nullptr, 0, 1, 0, 0, 0, nullptr, nullptr);
        k_addln<<<M, 256>>>(X, Q, ln1g + (size_t)l * DMODEL, ln1b + (size_t)l * DMODEL,
                            X, XR);

        // FFN
        dim3 gff1(FFDIM / 128, M / 128, 1);
        k_mma<<<gff1, 256, MMA_SMEM>>>(M, FFDIM, DMODEL, XR, DMODEL, 0, 0,
                                       WR + OFF_W1 + (size_t)l * FFDIM * DMODEL, DMODEL, 0, 0,
                                       Hf, FFDIM, 0, 0,
                                       b1 + (size_t)l * FFDIM, 0, 1, 1 /*gelu*/, 1, 0,
                                       nullptr, nullptr);
        dim3 gff2(DMODEL / 128, M / 128, 1);
        k_mma<<<gff2, 256, MMA_SMEM>>>(M, DMODEL, FFDIM, Hf, FFDIM, 0, 0,
                                       WR + OFF_W2 + (size_t)l * DMODEL * FFDIM, FFDIM, 0, 0,
                                       Q, DMODEL, 0, 0,
                                       b2 + (size_t)l * DMODEL, 0, 1, 0, 0, 0,
                                       nullptr, nullptr);

        float* dst = (l == NLAYER - 1) ? (float*)d_out : X;
        k_addln<<<M, 256>>>(X, Q, ln2g + (size_t)l * DMODEL, ln2b + (size_t)l * DMODEL,
                            dst, XR);
    }
}

// round 14
// speedup vs baseline: 1.1929x; 1.0858x over previous
#include <cuda_runtime.h>
#include <math.h>
#include <stdint.h>

#define BATCHN 4
#define SEQ    1024
#define DMODEL 1024
#define NHEAD  16
#define DHEAD  64
#define FFDIM  4096
#define NLAYER 4
#define MAXKLEN 1664
#define ROFF   640          // MAXKLEN - SEQ

// ---------------- scratch (device globals: allocation-free) ----------------
__device__ float g_X  [BATCHN*SEQ*DMODEL];   // residual stream (pure fp32)
__device__ float g_XR [BATCHN*SEQ*DMODEL];   // tf32-rounded copy of X
__device__ float g_QKV[BATCHN*SEQ*3*DMODEL]; // fused q|k|v (rounded), row stride 3072
__device__ float g_RQ [BATCHN*SEQ*DMODEL];   // q + r_w_bias (rounded)
__device__ float g_Q  [BATCHN*SEQ*DMODEL];   // Wo / FF2 outputs
__device__ float g_T  [BATCHN*SEQ*DMODEL];   // attention output
__device__ float g_P  [(size_t)BATCHN*NHEAD*SEQ*SEQ + 64]; // q@re^T+rb (+pad)
__device__ float g_H  [BATCHN*SEQ*FFDIM];              // FF hidden
__device__ float g_WR [56u*1024*1024];                 // tf32-rounded weights

// offsets (floats) into g_WR
#define OFF_QKV 0u                      // [l][3*D][D] stacked wq|wk|wv
#define OFF_WO  (12u*1024*1024)
#define OFF_W1  (16u*1024*1024)
#define OFF_W2  (32u*1024*1024)
#define OFF_RE  (48u*1024*1024)
#define RE_SZ   (NLAYER*NHEAD*MAXKLEN*DHEAD)   // 6,815,744

// ---------------- helpers ----------------
__device__ __forceinline__ float gelu_exact(float x) {
    return 0.5f * x * (1.0f + erff(x * 0.70710678118654752f));
}

__device__ __forceinline__ float rnd_tf32(float x) {
    uint32_t u;
    asm("cvt.rna.tf32.f32 %0, %1;" : "=r"(u) : "f"(x));
    return __uint_as_float(u);
}

__device__ __forceinline__ void mma_tf32(float c[4],
                                         uint32_t a0, uint32_t a1, uint32_t a2, uint32_t a3,
                                         uint32_t b0, uint32_t b1) {
    asm volatile(
        "mma.sync.aligned.m16n8k8.row.col.f32.tf32.tf32.f32 "
        "{%0,%1,%2,%3}, {%4,%5,%6,%7}, {%8,%9}, {%0,%1,%2,%3};"
        : "+f"(c[0]), "+f"(c[1]), "+f"(c[2]), "+f"(c[3])
        : "r"(a0), "r"(a1), "r"(a2), "r"(a3), "r"(b0), "r"(b1));
}

__device__ __forceinline__ uint32_t sptr(const void* p) {
    return (uint32_t)__cvta_generic_to_shared(p);
}
__device__ __forceinline__ void cpasync16(uint32_t s, const void* g) {
    asm volatile("cp.async.cg.shared.global [%0], [%1], 16;\n" :: "r"(s), "l"(g));
}
__device__ __forceinline__ void cpcommit() { asm volatile("cp.async.commit_group;\n"); }

// ldmatrix of four 8x8 32-bit-granule tiles (b16 form, standard tf32 trick)
__device__ __forceinline__ void ldsm_x4(uint32_t& a, uint32_t& b,
                                        uint32_t& c, uint32_t& d, uint32_t addr) {
    asm volatile("ldmatrix.sync.aligned.m8n8.x4.shared.b16 {%0,%1,%2,%3}, [%4];"
                 : "=r"(a), "=r"(b), "=r"(c), "=r"(d) : "r"(addr));
}

__device__ __forceinline__ float block_sum(float x, float* sm) {
    #pragma unroll
    for (int o = 16; o > 0; o >>= 1) x += __shfl_xor_sync(0xffffffffu, x, o);
    if ((threadIdx.x & 31) == 0) sm[threadIdx.x >> 5] = x;
    __syncthreads();
    float t = 0.f;
    #pragma unroll
    for (int w = 0; w < 8; w++) t += sm[w];
    __syncthreads();
    return t;
}

// ---------------- tf32 pre-rounding ----------------
__global__ void __launch_bounds__(256) k_round(const float4* __restrict__ src,
                                               float4* __restrict__ dst, int n4) {
    int i = blockIdx.x * blockDim.x + threadIdx.x;
    if (i < n4) {
        float4 v = src[i];
        v.x = rnd_tf32(v.x); v.y = rnd_tf32(v.y);
        v.z = rnd_tf32(v.z); v.w = rnd_tf32(v.w);
        dst[i] = v;
    }
}

// ---------------- embed gather (pure + rounded copies) ----------------
__global__ void __launch_bounds__(256) k_embed(const int* __restrict__ seq,
                                               const float* __restrict__ emb,
                                               float* __restrict__ X,
                                               float* __restrict__ XR) {
    int row = blockIdx.x;
    int tok = seq[row];
    const float4* src = (const float4*)(emb + (size_t)tok * DMODEL);
    float4 v = src[threadIdx.x];
    ((float4*)(X + (size_t)row * DMODEL))[threadIdx.x] = v;
    v.x = rnd_tf32(v.x); v.y = rnd_tf32(v.y);
    v.z = rnd_tf32(v.z); v.w = rnd_tf32(v.w);
    ((float4*)(XR + (size_t)row * DMODEL))[threadIdx.x] = v;
}

// ---------------- TF32 tensor-core GEMM, 3-stage cp.async pipeline ---------
// C[M,N] = A[M,K] @ B[N,K]^T. Block 128x128x16, 128 thr = 2x2 warps of
// 64x64 warp tiles (4 MMA per ldsm, 64 MMAs/warp/k-tile).
// All operands pre-rounded tf32 bit patterns -> mainloop is ldsm+MMA only.
// Dynamic smem: As[3][128][20] | Bs[3][128][20] = 61440 B.
// rqout: cols<1024 additionally write rnd(v + rwbv[c]). skew: skip bx+by<=6.
__global__ void __launch_bounds__(128) k_mma(
    int M, int N, int K,
    const float* __restrict__ A, int lda, long long sAb, long long sAh,
    const float* __restrict__ B, int ldb, long long sBb, long long sBh,
    float* __restrict__ C, int ldc, long long sCb, long long sCh,
    const float* __restrict__ bias, long long sbias_h,
    int Hdiv, int act, int rnd, int skew,
    float* __restrict__ rqout, const float* __restrict__ rwbv)
{
    if (skew && (int)(blockIdx.x + blockIdx.y) <= 6) return;

    constexpr int BM = 128, BN = 128, BK = 16;
    constexpr int AST = BK + 4;                 // 20
    constexpr int BST = BK + 4;
    extern __shared__ float smem[];
    float* As = smem;                           // [3][BM][AST]
    float* Bs = smem + 3 * BM * AST;            // [3][BN][BST]

    int z = blockIdx.z;
    int bb = z / Hdiv, hh = z % Hdiv;
    A += (long long)bb * sAb + (long long)hh * sAh;
    B += (long long)bb * sBb + (long long)hh * sBh;
    C += (long long)bb * sCb + (long long)hh * sCh;
    if (bias) bias += (long long)hh * sbias_h;

    const int tid  = threadIdx.x;
    const int lane = tid & 31, wid = tid >> 5;   // 4 warps
    const int gid  = lane >> 2, tig = lane & 3;
    const int wm   = wid & 1,   wn  = wid >> 1;  // 2x2 warp grid
    const int m0 = blockIdx.y * BM, n0 = blockIdx.x * BN;

    float acc[4][8][4];
    #pragma unroll
    for (int i = 0; i < 4; i++)
        #pragma unroll
        for (int j = 0; j < 8; j++)
            #pragma unroll
            for (int q = 0; q < 4; q++) acc[i][j][q] = 0.f;

    const int iters = K / BK;

    auto stage = [&](int it, int buf) {
        int k0 = it * BK;
        float* Ab = As + buf * BM * AST;
        float* Bb = Bs + buf * BN * BST;
        #pragma unroll
        for (int i = 0; i < 4; i++) {           // 128*16/4/128 = 4
            int idx = tid + i * 128;
            int r = idx >> 2, c4 = idx & 3;
            cpasync16(sptr(&Ab[r * AST + c4 * 4]),
                      A + (long long)(m0 + r) * lda + k0 + c4 * 4);
        }
        #pragma unroll
        for (int i = 0; i < 4; i++) {
            int idx = tid + i * 128;
            int r = idx >> 2, c4 = idx & 3;
            cpasync16(sptr(&Bb[r * BST + c4 * 4]),
                      B + (long long)(n0 + r) * ldb + k0 + c4 * 4);
        }
        cpcommit();
    };

    const int a_row = lane & 15;
    const int a_koff = (lane >> 4) * 4;
    const int b_t = lane >> 3;
    const int b_j = lane & 7;

    auto compute = [&](int buf) {
        float* Ab = As + buf * BM * AST;
        float* Bb = Bs + buf * BN * BST;
        #pragma unroll
        for (int ks = 0; ks < 2; ks++) {
            int kk = ks * 8;
            uint32_t af[4][4], bf[8][2];
            #pragma unroll
            for (int mt = 0; mt < 4; mt++) {
                int rm = wm * 64 + mt * 16;
                ldsm_x4(af[mt][0], af[mt][1], af[mt][2], af[mt][3],
                        sptr(&Ab[(rm + a_row) * AST + kk + a_koff]));
            }
            #pragma unroll
            for (int np = 0; np < 4; np++) {
                int nb = wn * 64 + np * 16;
                ldsm_x4(bf[2 * np][0], bf[2 * np][1],
                        bf[2 * np + 1][0], bf[2 * np + 1][1],
                        sptr(&Bb[(nb + (b_t >> 1) * 8 + b_j) * BST
                                 + kk + (b_t & 1) * 4]));
            }
            #pragma unroll
            for (int mt = 0; mt < 4; mt++)
                #pragma unroll
                for (int nt = 0; nt < 8; nt++)
                    mma_tf32(acc[mt][nt], af[mt][0], af[mt][1], af[mt][2], af[mt][3],
                             bf[nt][0], bf[nt][1]);
        }
    };

    stage(0, 0);
    stage(1, 1);
    for (int it = 0; it < iters; ++it) {
        if (it + 1 < iters) {
            asm volatile("cp.async.wait_group 1;\n");
        } else {
            asm volatile("cp.async.wait_group 0;\n");
        }
        __syncthreads();
        if (it + 2 < iters) stage(it + 2, (it + 2) % 3);
        compute(it % 3);
    }

    // epilogue
    #pragma unroll
    for (int mt = 0; mt < 4; mt++) {
        int r0 = m0 + wm * 64 + mt * 16 + gid;
        #pragma unroll
        for (int nt = 0; nt < 8; nt++) {
            int c = n0 + wn * 64 + nt * 8 + 2 * tig;
            float v0 = acc[mt][nt][0], v1 = acc[mt][nt][1];
            float v2 = acc[mt][nt][2], v3 = acc[mt][nt][3];
            if (bias) {
                float q0 = bias[c], q1 = bias[c + 1];
                v0 += q0; v1 += q1; v2 += q0; v3 += q1;
            }
            if (act) {
                v0 = gelu_exact(v0); v1 = gelu_exact(v1);
                v2 = gelu_exact(v2); v3 = gelu_exact(v3);
            }
            if (rnd) {
                v0 = rnd_tf32(v0); v1 = rnd_tf32(v1);
                v2 = rnd_tf32(v2); v3 = rnd_tf32(v3);
            }
            *(float2*)(C + (long long)r0 * ldc + c)       = make_float2(v0, v1);
            *(float2*)(C + (long long)(r0 + 8) * ldc + c) = make_float2(v2, v3);
            if (rqout && c < DMODEL) {
                float w0 = rwbv[c], w1 = rwbv[c + 1];
                *(float2*)(rqout + (long long)r0 * DMODEL + c) =
                    make_float2(rnd_tf32(v0 + w0), rnd_tf32(v1 + w1));
                *(float2*)(rqout + (long long)(r0 + 8) * DMODEL + c) =
                    make_float2(rnd_tf32(v2 + w0), rnd_tf32(v3 + w1));
            }
        }
    }
}

// ---------------- fused flash attention: softmax((RQ·K^T + shift(P))/4)·V ----
// 128 threads = 4 warps, each warp owns 16 query rows (BM=64 per CTA).
// Double-buffered K/V/P staging via cp.async; P band prefetched to smem.
// P staged/added only for tiles with nt <= blockIdx.x (others provably unused).
// Dynamic smem: Ks[2][64][68] | Vs[2][64][72] | Ps[2][64][72] = 108544 B.
__global__ void __launch_bounds__(128) k_flash(
    const float* __restrict__ RQg, const float* __restrict__ Kg,
    const float* __restrict__ Vg,  const float* __restrict__ Pg,
    float* __restrict__ Tg, int ldkv)
{
    extern __shared__ float fsm[];
    float* KsB = fsm;                         // [2][64][68]; buf also holds p tile
    float* VsB = fsm + 2 * 64 * 68;           // [2][64][72]
    float* PsB = fsm + 2 * 64 * 68 + 2 * 64 * 72;  // [2][64][72] staged P band
    #define KS(b, r, c) KsB[(b) * 64 * 68 + (r) * 68 + (c)]
    #define VS(b, r, c) VsB[(b) * 64 * 72 + (r) * 72 + (c)]
    #define PS(b, r, c) PsB[(b) * 64 * 72 + (r) * 72 + (c)]

    const int z  = blockIdx.y;             // b*H + h
    const int bb = z >> 4, hh = z & 15;
    const int m0 = blockIdx.x * 64;
    const float* rq = RQg + (size_t)bb * SEQ * DMODEL + hh * DHEAD;
    const float* kp = Kg  + (size_t)bb * SEQ * ldkv + hh * DHEAD;
    const float* vp = Vg  + (size_t)bb * SEQ * ldkv + hh * DHEAD;
    const float* pp = Pg  + (size_t)z * SEQ * SEQ;
    float*       tp = Tg  + (size_t)bb * SEQ * DMODEL + hh * DHEAD;

    const int tid = threadIdx.x, lane = tid & 31, wid = tid >> 5;
    const int gid = lane >> 2, tig = lane & 3;
    const int a_row = lane & 15, a_koff = (lane >> 4) * 4;
    const int b_t = lane >> 3, b_j = lane & 7;
    const int w16 = wid * 16;
    const int mg0 = m0 + w16 + gid, mg1 = mg0 + 8;
    const int offp = (1023 - mg0) & 3;     // P band alignment offset (== for mg1)

    // ---- stage RQ tile into Ks buf0, ldsm into registers ----
    #pragma unroll
    for (int i = 0; i < 8; i++) {
        int idx = tid + i * 128;
        int r = idx >> 4, c4 = idx & 15;
        cpasync16(sptr(&KS(0, r, c4 * 4)), rq + (size_t)(m0 + r) * DMODEL + c4 * 4);
    }
    cpcommit();
    asm volatile("cp.async.wait_group 0;\n");
    __syncthreads();
    uint32_t aq[8][4];
    #pragma unroll
    for (int ks = 0; ks < 8; ks++)
        ldsm_x4(aq[ks][0], aq[ks][1], aq[ks][2], aq[ks][3],
                sptr(&KS(0, w16 + a_row, ks * 8 + a_koff)));
    __syncthreads();   // aq reads done before buf0 is overwritten

    // stage K/V tile (+ P band when used) for key-tile nt into buffer b
    auto stage = [&](int nt, int b) {
        int n0 = nt * 64;
        #pragma unroll
        for (int i = 0; i < 8; i++) {
            int idx = tid + i * 128;
            int r = idx >> 4, c4 = idx & 15;
            cpasync16(sptr(&KS(b, r, c4 * 4)), kp + (size_t)(n0 + r) * ldkv + c4 * 4);
            cpasync16(sptr(&VS(b, r, c4 * 4)), vp + (size_t)(n0 + r) * ldkv + c4 * 4);
        }
        // P band only read when some n <= m in tile, i.e. nt <= blockIdx.x
        if (nt <= (int)blockIdx.x) {
            #pragma unroll
            for (int i = 0; i < 9; i++) {
                int idx = tid + i * 128;
                if (idx < 1088) {
                    int r = idx / 17, ch = idx % 17;
                    int m = m0 + r;
                    int cs = n0 - m + 1023;
                    int as = cs & ~3;
                    cpasync16(sptr(&PS(b, r, ch * 4)),
                              pp + (size_t)m * SEQ + as + ch * 4);
                }
            }
        }
        cpcommit();
    };

    float accO[8][4];
    #pragma unroll
    for (int ng = 0; ng < 8; ng++)
        #pragma unroll
        for (int q = 0; q < 4; q++) accO[ng][q] = 0.f;
    float mrow0 = -1e30f, mrow1 = -1e30f, lrow0 = 0.f, lrow1 = 0.f;

    stage(0, 0);
    for (int nt = 0; nt < SEQ / 64; nt++) {
        const int n0 = nt * 64;
        const int b = nt & 1;
        asm volatile("cp.async.wait_group 0;\n");   // tile nt loaded
        __syncthreads();                            // visible; prev compute done
        if (nt + 1 < SEQ / 64) stage(nt + 1, b ^ 1);  // overlaps compute(nt)

        // ---- S = RQ · K^T ----
        float S[8][4];
        #pragma unroll
        for (int ng = 0; ng < 8; ng++)
            #pragma unroll
            for (int q = 0; q < 4; q++) S[ng][q] = 0.f;
        #pragma unroll
        for (int ks = 0; ks < 8; ks++) {
            uint32_t bf[8][2];
            #pragma unroll
            for (int np = 0; np < 4; np++)
                ldsm_x4(bf[2 * np][0], bf[2 * np][1],
                        bf[2 * np + 1][0], bf[2 * np + 1][1],
                        sptr(&KS(b, np * 16 + (b_t >> 1) * 8 + b_j,
                                 ks * 8 + (b_t & 1) * 4)));
            #pragma unroll
            for (int ng = 0; ng < 8; ng++)
                mma_tf32(S[ng], aq[ks][0], aq[ks][1], aq[ks][2], aq[ks][3],
                         bf[ng][0], bf[ng][1]);
        }

        // ---- add shifted P (from staged smem band), scale ----
        if (nt <= (int)blockIdx.x) {
            #pragma unroll
            for (int ng = 0; ng < 8; ng++) {
                int j = ng * 8 + 2 * tig;
                int nc = n0 + j;
                float p0 = PS(b, w16 + gid,     offp + j);
                float p1 = PS(b, w16 + gid,     offp + j + 1);
                float p2 = PS(b, w16 + gid + 8, offp + j);
                float p3 = PS(b, w16 + gid + 8, offp + j + 1);
                if (nc     <= mg0) S[ng][0] += p0;
                if (nc + 1 <= mg0) S[ng][1] += p1;
                if (nc     <= mg1) S[ng][2] += p2;
                if (nc + 1 <= mg1) S[ng][3] += p3;
            }
        }
        #pragma unroll
        for (int ng = 0; ng < 8; ng++) {
            S[ng][0] *= 0.25f; S[ng][1] *= 0.25f;
            S[ng][2] *= 0.25f; S[ng][3] *= 0.25f;
        }

        // ---- online softmax update ----
        float tm0 = -1e30f, tm1 = -1e30f;
        #pragma unroll
        for (int ng = 0; ng < 8; ng++) {
            tm0 = fmaxf(tm0, fmaxf(S[ng][0], S[ng][1]));
            tm1 = fmaxf(tm1, fmaxf(S[ng][2], S[ng][3]));
        }
        tm0 = fmaxf(tm0, __shfl_xor_sync(0xffffffffu, tm0, 1));
        tm0 = fmaxf(tm0, __shfl_xor_sync(0xffffffffu, tm0, 2));
        tm1 = fmaxf(tm1, __shfl_xor_sync(0xffffffffu, tm1, 1));
        tm1 = fmaxf(tm1, __shfl_xor_sync(0xffffffffu, tm1, 2));
        float mn0 = fmaxf(mrow0, tm0), mn1 = fmaxf(mrow1, tm1);
        float al0 = __expf(mrow0 - mn0), al1 = __expf(mrow1 - mn1);
        mrow0 = mn0; mrow1 = mn1;
        float ts0 = 0.f, ts1 = 0.f;
        #pragma unroll
        for (int ng = 0; ng < 8; ng++) {
            S[ng][0] = __expf(S[ng][0] - mn0); ts0 += S[ng][0];
            S[ng][1] = __expf(S[ng][1] - mn0); ts0 += S[ng][1];
            S[ng][2] = __expf(S[ng][2] - mn1); ts1 += S[ng][2];
            S[ng][3] = __expf(S[ng][3] - mn1); ts1 += S[ng][3];
        }
        ts0 += __shfl_xor_sync(0xffffffffu, ts0, 1);
        ts0 += __shfl_xor_sync(0xffffffffu, ts0, 2);
        ts1 += __shfl_xor_sync(0xffffffffu, ts1, 1);
        ts1 += __shfl_xor_sync(0xffffffffu, ts1, 2);
        lrow0 = lrow0 * al0 + ts0;
        lrow1 = lrow1 * al1 + ts1;
        #pragma unroll
        for (int ng = 0; ng < 8; ng++) {
            accO[ng][0] *= al0; accO[ng][1] *= al0;
            accO[ng][2] *= al1; accO[ng][3] *= al1;
        }

        // ---- p tile -> smem (overlay Ks[b]), own-warp rows only ----
        __syncthreads();    // all warps done reading Ks[b]
        #pragma unroll
        for (int ng = 0; ng < 8; ng++) {
            *(float2*)&KS(b, w16 + gid,     ng * 8 + 2 * tig) =
                make_float2(rnd_tf32(S[ng][0]), rnd_tf32(S[ng][1]));
            *(float2*)&KS(b, w16 + gid + 8, ng * 8 + 2 * tig) =
                make_float2(rnd_tf32(S[ng][2]), rnd_tf32(S[ng][3]));
        }
        __syncwarp();

        // ---- O += p · V ----
        #pragma unroll
        for (int ks = 0; ks < 8; ks++) {
            uint32_t ap0, ap1, ap2, ap3;
            ldsm_x4(ap0, ap1, ap2, ap3,
                    sptr(&KS(b, w16 + a_row, ks * 8 + a_koff)));
            #pragma unroll
            for (int ng = 0; ng < 8; ng++) {
                uint32_t b0 = __float_as_uint(VS(b, ks * 8 + tig,     ng * 8 + gid));
                uint32_t b1 = __float_as_uint(VS(b, ks * 8 + tig + 4, ng * 8 + gid));
                mma_tf32(accO[ng], ap0, ap1, ap2, ap3, b0, b1);
            }
        }
    }

    // ---- normalize + write (rounded: feeds Wo GEMM) ----
    float i0 = 1.f / lrow0, i1 = 1.f / lrow1;
    #pragma unroll
    for (int ng = 0; ng < 8; ng++) {
        int c = ng * 8 + 2 * tig;
        *(float2*)(tp + (size_t)mg0 * DMODEL + c) =
            make_float2(rnd_tf32(accO[ng][0] * i0), rnd_tf32(accO[ng][1] * i0));
        *(float2*)(tp + (size_t)mg1 * DMODEL + c) =
            make_float2(rnd_tf32(accO[ng][2] * i1), rnd_tf32(accO[ng][3] * i1));
    }
    #undef KS
    #undef VS
    #undef PS
}

// ---------------- residual add + LayerNorm (pure dst + rounded copy) -------
__global__ void __launch_bounds__(256) k_addln(const float* __restrict__ X,
                                               const float* __restrict__ R,
                                               const float* __restrict__ g,
                                               const float* __restrict__ b,
                                               float* __restrict__ dst,
                                               float* __restrict__ dstR) {
    int row = blockIdx.x;
    size_t base = (size_t)row * DMODEL;
    int tid = threadIdx.x;
    __shared__ float sm[8];

    float v[4];
    float s = 0.f;
    #pragma unroll
    for (int q = 0; q < 4; q++) {
        int c = q * 256 + tid;
        float x = X[base + c] + R[base + c];
        v[q] = x; s += x;
    }
    float mu = block_sum(s, sm) * (1.f / DMODEL);
    float s2 = 0.f;
    #pragma unroll
    for (int q = 0; q < 4; q++) { float d = v[q] - mu; s2 += d * d; }
    float var = block_sum(s2, sm) * (1.f / DMODEL);
    float rs = rsqrtf(var + 1e-5f);
    #pragma unroll
    for (int q = 0; q < 4; q++) {
        int c = q * 256 + tid;
        float y = (v[q] - mu) * rs * g[c] + b[c];
        dst[base + c] = y;
        dstR[base + c] = rnd_tf32(y);
    }
}

// ---------------- orchestration ----------------
extern "C" void kernel_launch(void* const* d_in, const int* in_sizes, int n_in,
                              void* d_out, int out_size) {
    (void)in_sizes; (void)n_in; (void)out_size;
    const int*   seq    = (const int*)  d_in[0];
    // d_in[1] mask (all true), d_in[2] cmems, d_in[3] mems: unused by reference
    const float* embed  = (const float*)d_in[4];
    const float* Wq     = (const float*)d_in[5];
    const float* Wk     = (const float*)d_in[6];
    const float* Wv     = (const float*)d_in[7];
    const float* Wo     = (const float*)d_in[8];
    const float* r_emb  = (const float*)d_in[9];
    const float* rwb    = (const float*)d_in[10];
    const float* r_bias = (const float*)d_in[11];
    const float* ln1g   = (const float*)d_in[12];
    const float* ln1b   = (const float*)d_in[13];
    const float* ln2g   = (const float*)d_in[14];
    const float* ln2b   = (const float*)d_in[15];
    const float* w1     = (const float*)d_in[16];
    const float* b1     = (const float*)d_in[17];
    const float* w2     = (const float*)d_in[18];
    const float* b2     = (const float*)d_in[19];

    float *X, *XR, *QKV, *RQ, *Q, *T, *P, *Hf, *WR;
    cudaGetSymbolAddress((void**)&X,   g_X);
    cudaGetSymbolAddress((void**)&XR,  g_XR);
    cudaGetSymbolAddress((void**)&QKV, g_QKV);
    cudaGetSymbolAddress((void**)&RQ,  g_RQ);
    cudaGetSymbolAddress((void**)&Q,   g_Q);
    cudaGetSymbolAddress((void**)&T,   g_T);
    cudaGetSymbolAddress((void**)&P,   g_P);
    cudaGetSymbolAddress((void**)&Hf,  g_H);
    cudaGetSymbolAddress((void**)&WR,  g_WR);

    static const int MMA_SMEM = 61440;
    static const int FLASH_SMEM = (2 * 64 * 68 + 2 * 64 * 72 + 2 * 64 * 72) * 4; // 108544
    cudaFuncSetAttribute(k_mma, cudaFuncAttributeMaxDynamicSharedMemorySize, MMA_SMEM);
    cudaFuncSetAttribute(k_flash, cudaFuncAttributeMaxDynamicSharedMemorySize, FLASH_SMEM);

    auto roundArr = [&](const float* src, float* dst, size_t n) {
        int n4 = (int)(n / 4);
        k_round<<<(n4 + 255) / 256, 256>>>((const float4*)src, (float4*)dst, n4);
    };
    // stack wq|wk|wv per layer into [3*D, D]
    const size_t WSZ = (size_t)DMODEL * DMODEL;
    for (int l = 0; l < NLAYER; l++) {
        float* dst = WR + OFF_QKV + (size_t)l * 3 * WSZ;
        roundArr(Wq + (size_t)l * WSZ, dst,           WSZ);
        roundArr(Wk + (size_t)l * WSZ, dst + WSZ,     WSZ);
        roundArr(Wv + (size_t)l * WSZ, dst + 2 * WSZ, WSZ);
    }
    roundArr(Wo, WR + OFF_WO, (size_t)NLAYER * WSZ);
    roundArr(w1, WR + OFF_W1, (size_t)NLAYER * FFDIM * DMODEL);
    roundArr(w2, WR + OFF_W2, (size_t)NLAYER * DMODEL * FFDIM);
    roundArr(r_emb, WR + OFF_RE, (size_t)RE_SZ);

    const int M = BATCHN * SEQ;                       // 4096
    const long long sQKVb = (long long)SEQ * 3 * DMODEL;
    const long long sSCb  = (long long)NHEAD * SEQ * SEQ;
    const long long sSCh  = (long long)SEQ * SEQ;

    k_embed<<<M, 256>>>(seq, embed, X, XR);

    for (int l = 0; l < NLAYER; l++) {
        // fused QKV projection (N=3072) + rwb epilogue -> RQ
        dim3 gqkv(3 * DMODEL / 128, M / 128, 1);      // (24,32)
        k_mma<<<gqkv, 128, MMA_SMEM>>>(M, 3 * DMODEL, DMODEL,
                                       XR, DMODEL, 0, 0,
                                       WR + OFF_QKV + (size_t)l * 3 * WSZ, DMODEL, 0, 0,
                                       QKV, 3 * DMODEL, 0, 0,
                                       nullptr, 0, 1, 0, 1 /*rnd*/, 0,
                                       RQ, rwb + (size_t)l * NHEAD * DHEAD);

        // P = q @ re^T + rb (skewed); skip blocks never read (bx+by <= 6)
        dim3 gsc(SEQ / 128, SEQ / 128, BATCHN * NHEAD);
        k_mma<<<gsc, 128, MMA_SMEM>>>(SEQ, SEQ, DHEAD,
                                      QKV, 3 * DMODEL, sQKVb, DHEAD,
                                      WR + OFF_RE + ((size_t)l * NHEAD * MAXKLEN + ROFF) * DHEAD,
                                      DHEAD, 0, (long long)MAXKLEN * DHEAD,
                                      P, SEQ, sSCb, sSCh,
                                      r_bias + (size_t)l * NHEAD * MAXKLEN + ROFF,
                                      MAXKLEN, NHEAD, 0, 0, 1, nullptr, nullptr);

        // fused attention: T = softmax((RQ K^T + shift(P))/4) V
        dim3 gfl(SEQ / 64, BATCHN * NHEAD, 1);
        k_flash<<<gfl, 128, FLASH_SMEM>>>(RQ, QKV + DMODEL, QKV + 2 * DMODEL, P, T,
                                          3 * DMODEL);

        // output projection -> Q, residual + LN1 -> X (+XR)
        dim3 gproj(DMODEL / 128, M / 128, 1);
        k_mma<<<gproj, 128, MMA_SMEM>>>(M, DMODEL, DMODEL, T, DMODEL, 0, 0,
                                        WR + OFF_WO + (size_t)l * WSZ, DMODEL, 0, 0,
                                        Q, DMODEL, 0, 0,
                                        nullptr, 0, 1, 0, 0, 0, nullptr, nullptr);
        k_addln<<<M, 256>>>(X, Q, ln1g + (size_t)l * DMODEL, ln1b + (size_t)l * DMODEL,
                            X, XR);

        // FFN
        dim3 gff1(FFDIM / 128, M / 128, 1);
        k_mma<<<gff1, 128, MMA_SMEM>>>(M, FFDIM, DMODEL, XR, DMODEL, 0, 0,
                                       WR + OFF_W1 + (size_t)l * FFDIM * DMODEL, DMODEL, 0, 0,
                                       Hf, FFDIM, 0, 0,
                                       b1 + (size_t)l * FFDIM, 0, 1, 1 /*gelu*/, 1, 0,
                                       nullptr, nullptr);
        dim3 gff2(DMODEL / 128, M / 128, 1);
        k_mma<<<gff2, 128, MMA_SMEM>>>(M, DMODEL, FFDIM, Hf, FFDIM, 0, 0,
                                       WR + OFF_W2 + (size_t)l * DMODEL * FFDIM, FFDIM, 0, 0,
                                       Q, DMODEL, 0, 0,
                                       b2 + (size_t)l * DMODEL, 0, 1, 0, 0, 0,
                                       nullptr, nullptr);

        float* dst = (l == NLAYER - 1) ? (float*)d_out : X;
        k_addln<<<M, 256>>>(X, Q, ln2g + (size_t)l * DMODEL, ln2b + (size_t)l * DMODEL,
                            dst, XR);
    }
}